// round 16
// baseline (speedup 1.0000x reference)
#include <cuda_runtime.h>
#include <cstdint>

typedef unsigned long long u64;

#define NPIX 32768
#define PSTRIDE 2048

// ---------------- scratch ----------------
__device__ float g_bufA[NPIX*324];
__device__ float g_bufB[NPIX*324];
__device__ float g_bufC[NPIX*324];
__device__ float g_bufD[NPIX*324];
__device__ float g_bufE[NPIX*324];

// transposed partials: [pos][blk], stride 2048
__device__ float g_psum0[324*PSTRIDE];
__device__ float g_psq0 [324*PSTRIDE];
__device__ float g_psum1[324*PSTRIDE];
__device__ float g_psq1 [324*PSTRIDE];
__device__ float g_scale[12][324];
__device__ float g_shift[12][324];

// ---------------- f32x2 helpers ----------------
__device__ __forceinline__ u64 pk2(float lo, float hi){ u64 r; asm("mov.b64 %0,{%1,%2};":"=l"(r):"f"(lo),"f"(hi)); return r; }
__device__ __forceinline__ u64 dup2(float v){ return pk2(v, v); }
__device__ __forceinline__ void fma2(u64 &d, u64 a, u64 b){ asm("fma.rn.f32x2 %0,%1,%2,%0;":"+l"(d):"l"(a),"l"(b)); }
__device__ __forceinline__ void unpk2(float &lo, float &hi, u64 v){ asm("mov.b64 {%0,%1},%2;":"=f"(lo),"=f"(hi):"l"(v)); }

#define FMA9(acc, xd, vbase) { \
  const ulonglong2* _vv = (const ulonglong2*)(vbase); \
  ulonglong2 _a0=_vv[0], _a1=_vv[1], _a2=_vv[2], _a3=_vv[3]; \
  u64 _a8 = ((const u64*)(vbase))[8]; \
  fma2(acc[0],xd,_a0.x); fma2(acc[1],xd,_a0.y); \
  fma2(acc[2],xd,_a1.x); fma2(acc[3],xd,_a1.y); \
  fma2(acc[4],xd,_a2.x); fma2(acc[5],xd,_a2.y); \
  fma2(acc[6],xd,_a3.x); fma2(acc[7],xd,_a3.y); \
  fma2(acc[8],xd,_a8); }

// m[0..7] += ud * X[p][0..15] (16 contiguous floats, 4x LDS.128)
#define FMA8X(m, ud, xb) { \
  const ulonglong2* _xp = (const ulonglong2*)(xb); \
  ulonglong2 _x0=_xp[0], _x1=_xp[1], _x2=_xp[2], _x3=_xp[3]; \
  fma2(m[0],ud,_x0.x); fma2(m[1],ud,_x0.y); \
  fma2(m[2],ud,_x1.x); fma2(m[3],ud,_x1.y); \
  fma2(m[4],ud,_x2.x); fma2(m[5],ud,_x2.y); \
  fma2(m[6],ud,_x3.x); fma2(m[7],ud,_x3.y); }

#define ST9(dst, acc) { \
  ulonglong2* _dd=(ulonglong2*)(dst); \
  _dd[0]=make_ulonglong2(acc[0],acc[1]); _dd[1]=make_ulonglong2(acc[2],acc[3]); \
  _dd[2]=make_ulonglong2(acc[4],acc[5]); _dd[3]=make_ulonglong2(acc[6],acc[7]); \
  ((u64*)(dst))[8]=acc[8]; }

#define LD9BIAS(yacc, bptr) { \
  const ulonglong2* _bb = (const ulonglong2*)(bptr); \
  ulonglong2 _b0=_bb[0], _b1=_bb[1], _b2=_bb[2], _b3=_bb[3]; \
  yacc[0]=_b0.x; yacc[1]=_b0.y; yacc[2]=_b1.x; yacc[3]=_b1.y; \
  yacc[4]=_b2.x; yacc[5]=_b2.y; yacc[6]=_b3.x; yacc[7]=_b3.y; \
  yacc[8]=((const u64*)(bptr))[8]; }

// gather 4 consecutive logical elements (c4..c4+3) of a pixel from pitch-20 rows
__device__ __forceinline__ float4 gather4(const float* sNp, int c4) {
    float4 o;
    int r0 = (c4+0)/18; o.x = sNp[r0*20 + (c4+0) - r0*18];
    int r1 = (c4+1)/18; o.y = sNp[r1*20 + (c4+1) - r1*18];
    int r2 = (c4+2)/18; o.z = sNp[r2*20 + (c4+2) - r2*18];
    int r3 = (c4+3)/18; o.w = sNp[r3*20 + (c4+3) - r3*18];
    return o;
}
// scatter 4 consecutive logical elements into pitch-20 rows
__device__ __forceinline__ void scatter4(float* sNp, int c4, float4 v) {
    int r0 = (c4+0)/18; sNp[r0*20 + (c4+0) - r0*18] = v.x;
    int r1 = (c4+1)/18; sNp[r1*20 + (c4+1) - r1*18] = v.y;
    int r2 = (c4+2)/18; sNp[r2*20 + (c4+2) - r2*18] = v.z;
    int r3 = (c4+3)/18; sNp[r3*20 + (c4+3) - r3*18] = v.w;
}

// phase1 with vector-loaded U row (pitch 20, 18 valid) against pitch-20 X rows
#define PHASE1_M9(m, Up, Xb) { \
  float4 _u; float2 _ue; \
  _u = *(const float4*)((Up)+0); \
  FMA9(m, dup2(_u.x), (Xb)+0*20); FMA9(m, dup2(_u.y), (Xb)+1*20); \
  FMA9(m, dup2(_u.z), (Xb)+2*20); FMA9(m, dup2(_u.w), (Xb)+3*20); \
  _u = *(const float4*)((Up)+4); \
  FMA9(m, dup2(_u.x), (Xb)+4*20); FMA9(m, dup2(_u.y), (Xb)+5*20); \
  FMA9(m, dup2(_u.z), (Xb)+6*20); FMA9(m, dup2(_u.w), (Xb)+7*20); \
  _u = *(const float4*)((Up)+8); \
  FMA9(m, dup2(_u.x), (Xb)+8*20); FMA9(m, dup2(_u.y), (Xb)+9*20); \
  FMA9(m, dup2(_u.z), (Xb)+10*20); FMA9(m, dup2(_u.w), (Xb)+11*20); \
  _u = *(const float4*)((Up)+12); \
  FMA9(m, dup2(_u.x), (Xb)+12*20); FMA9(m, dup2(_u.y), (Xb)+13*20); \
  FMA9(m, dup2(_u.z), (Xb)+14*20); FMA9(m, dup2(_u.w), (Xb)+15*20); \
  _ue = *(const float2*)((Up)+16); \
  FMA9(m, dup2(_ue.x), (Xb)+16*20); FMA9(m, dup2(_ue.y), (Xb)+17*20); }

// ---------------- dummy (profiler alignment) ----------------
__global__ void dummy_kernel() {}

// ---------------- f0: (U·X)·V order, vector U rows ----------------
__global__ void __launch_bounds__(288,4) f0_kernel(const float* __restrict__ x,
    const float* __restrict__ U0, const float* __restrict__ V0,
    const float* __restrict__ b0, float* __restrict__ out)
{
    extern __shared__ float sm[];
    float* sT  = sm;              // 18*260 = 4680
    float* sU  = sm + 4680;       // 864 (3 taps, global layout [tap3][a*16+p])
    float* sVp = sm + 5544;       // 960
    float* sN  = sm + 6504;       // 5760 -> total 12264 floats
    const int t = threadIdx.x;
    const int j = t % 18, pixl = t / 18;
    const int hx = blockIdx.x, b = blockIdx.y;
    const int h = hx >> 1, wbase = (hx & 1) << 4;
    const int gbid = b*64 + hx;

    u64 yacc[9];
    #pragma unroll
    for (int k = 0; k < 9; ++k) yacc[k] = *(const u64*)(b0 + j*18 + 2*k);

    for (int c = 0; c < 8; ++c) {
        const float* xc  = x  + (size_t)(b*8 + c)*262144;
        const float* U0c = U0 + c*2592;
        const float* V0c = V0 + c*2592;
        for (int di = 0; di < 3; ++di) {
            const int hr = h - 1 + di;
            for (int e = t; e < 864; e += 288)
                sU[e] = U0c[di*864 + e];          // direct copy [tap3][a*16+p]
            for (int e = t; e < 960; e += 288) {
                int tap3 = e/320, r = e%320, q = r/20, d = r%20;
                sVp[e] = (d < 18) ? V0c[((di*3 + tap3)*16 + q)*18 + d] : 0.f;
            }
            for (int e = t; e < 4608; e += 288) {
                int pq = e/18, col = e - (e/18)*18;
                int gw = wbase - 1 + col;
                float v = 0.f;
                if ((unsigned)hr < 32u && (unsigned)gw < 32u)
                    v = xc[pq*1024 + hr*32 + gw];
                sT[col*260 + pq] = v;
            }
            __syncthreads();
            #pragma unroll
            for (int dj = 0; dj < 3; ++dj) {
                const float* Xb = sT + (pixl + dj)*260;
                const float* Up = sU + dj*288 + j*16;
                u64 m[8];
                #pragma unroll
                for (int k = 0; k < 8; ++k) m[k] = 0ull;
                {
                    float4 u;
                    u = *(const float4*)(Up+0);
                    FMA8X(m, dup2(u.x), Xb + 0*16); FMA8X(m, dup2(u.y), Xb + 1*16);
                    FMA8X(m, dup2(u.z), Xb + 2*16); FMA8X(m, dup2(u.w), Xb + 3*16);
                    u = *(const float4*)(Up+4);
                    FMA8X(m, dup2(u.x), Xb + 4*16); FMA8X(m, dup2(u.y), Xb + 5*16);
                    FMA8X(m, dup2(u.z), Xb + 6*16); FMA8X(m, dup2(u.w), Xb + 7*16);
                    u = *(const float4*)(Up+8);
                    FMA8X(m, dup2(u.x), Xb + 8*16); FMA8X(m, dup2(u.y), Xb + 9*16);
                    FMA8X(m, dup2(u.z), Xb + 10*16); FMA8X(m, dup2(u.w), Xb + 11*16);
                    u = *(const float4*)(Up+12);
                    FMA8X(m, dup2(u.x), Xb + 12*16); FMA8X(m, dup2(u.y), Xb + 13*16);
                    FMA8X(m, dup2(u.z), Xb + 14*16); FMA8X(m, dup2(u.w), Xb + 15*16);
                }
                #pragma unroll
                for (int k = 0; k < 8; ++k) {
                    float m0, m1;
                    unpk2(m0, m1, m[k]);
                    FMA9(yacc, dup2(m0), sVp + dj*320 + (2*k)*20);
                    FMA9(yacc, dup2(m1), sVp + dj*320 + (2*k+1)*20);
                }
            }
            __syncthreads();
        }
    }
    ST9(sN + pixl*360 + j*20, yacc);
    __syncthreads();
    float* ob = out + ((size_t)(b*32 + h)*32 + wbase)*324;
    for (int e = t; e < 1296; e += 288) {
        int p_idx = e/81, c4 = (e - p_idx*81)*4;
        *(float4*)(ob + 4*e) = gather4(sN + p_idx*360, c4);
    }
    for (int e = t; e < 324; e += 288) {
        int a = e/18, d = e - a*18;
        float s = 0.f, ss = 0.f;
        #pragma unroll 4
        for (int pp = 0; pp < 16; ++pp) {
            float v = sN[pp*360 + a*20 + d];
            s += v; ss = fmaf(v, v, ss);
        }
        g_psum0[e*PSTRIDE + gbid] = s;
        g_psq0 [e*PSTRIDE + gbid] = ss;
    }
}

// ---------------- conv1x1 v3: register-M + vector U rows ----------------
__global__ void __launch_bounds__(288,3) conv1x1_kernel(
    const float* __restrict__ inA, int slotA,
    const float* __restrict__ inB, int slotB,
    const float* __restrict__ alpha_ptr,
    const float* __restrict__ U0w, const float* __restrict__ V0w,
    const float* __restrict__ b0w, float* __restrict__ out0,
    const float* __restrict__ U1w, const float* __restrict__ V1w,
    const float* __restrict__ b1w, float* __restrict__ out1)
{
    extern __shared__ float sm[];
    float* sV0  = sm;            // 360 [q*20+d]
    float* sV1  = sm + 360;      // 360
    float* sU0  = sm + 720;      // 360 [a*20+p]
    float* sU1  = sm + 1080;     // 360
    float* sB0  = sm + 1440;     // 360
    float* sB1  = sm + 1800;     // 360
    float* sScA = sm + 2160;     // 324
    float* sShA = sm + 2484;     // 324
    float* sScB = sm + 2808;     // 324
    float* sShB = sm + 3132;     // 324
    float* sXa  = sm + 3456;     // 5760
    float* sN   = sm + 9216;     // 5760 -> total 14976 floats = 59904 B
    const int t = threadIdx.x;
    const int j = t % 18, pixl = t / 18;
    const bool dual_in  = (inB  != nullptr);
    const bool dual_out = (out1 != nullptr);

    for (int e = t; e < 360; e += 288) {
        int q = e/20, d = e%20;
        sV0[e] = (d < 18) ? V0w[q*18 + d] : 0.f;
        sB0[e] = (d < 18) ? b0w[q*18 + d] : 0.f;
        sU0[e] = (d < 18) ? U0w[q*18 + d] : 0.f;   // row a=q, col p=d
        if (dual_out) {
            sV1[e] = (d < 18) ? V1w[q*18 + d] : 0.f;
            sB1[e] = (d < 18) ? b1w[q*18 + d] : 0.f;
            sU1[e] = (d < 18) ? U1w[q*18 + d] : 0.f;
        }
    }
    for (int e = t; e < 324; e += 288) {
        sScA[e] = g_scale[slotA][e];
        sShA[e] = g_shift[slotA][e];
        if (dual_in) { sScB[e] = g_scale[slotB][e]; sShB[e] = g_shift[slotB][e]; }
    }
    const float alpha = (!dual_in && alpha_ptr) ? *alpha_ptr : 1.f;
    __syncthreads();

    const size_t segbase = (size_t)blockIdx.x * 5184;
    const float* gA = inA + segbase;
    const float* gB = dual_in ? (inB + segbase) : nullptr;
    for (int e = t; e < 1296; e += 288) {
        float4 v = *(const float4*)(gA + 4*e);
        int px = e / 81, c4 = (e - px*81) * 4;
        float4 sc = *(const float4*)(sScA + c4);
        float4 sh = *(const float4*)(sShA + c4);
        float4 r;
        r.x = fmaf(v.x, sc.x, sh.x);
        r.y = fmaf(v.y, sc.y, sh.y);
        r.z = fmaf(v.z, sc.z, sh.z);
        r.w = fmaf(v.w, sc.w, sh.w);
        if (dual_in) {
            float4 vb  = *(const float4*)(gB + 4*e);
            float4 scb = *(const float4*)(sScB + c4);
            float4 shb = *(const float4*)(sShB + c4);
            r.x += fmaf(vb.x, scb.x, shb.x);
            r.y += fmaf(vb.y, scb.y, shb.y);
            r.z += fmaf(vb.z, scb.z, shb.z);
            r.w += fmaf(vb.w, scb.w, shb.w);
        } else {
            if (r.x < 0.f) r.x *= alpha;
            if (r.y < 0.f) r.y *= alpha;
            if (r.z < 0.f) r.z *= alpha;
            if (r.w < 0.f) r.w *= alpha;
        }
        scatter4(sXa + px*360, c4, r);
    }
    __syncthreads();

    for (int pass = 0; pass < (dual_out ? 2 : 1); ++pass) {
        const float* sV  = pass ? sV1 : sV0;
        const float* sU  = pass ? sU1 : sU0;
        const float* sBp = pass ? sB1 : sB0;
        float* outp      = pass ? out1 : out0;
        float* psum      = pass ? g_psum1 : g_psum0;
        float* psq       = pass ? g_psq1  : g_psq0;

        u64 m[9];
        #pragma unroll
        for (int k = 0; k < 9; ++k) m[k] = 0ull;
        const float* Xb = sXa + pixl*360;
        const float* Up = sU + j*20;
        PHASE1_M9(m, Up, Xb);

        u64 yacc[9];
        LD9BIAS(yacc, sBp + j*20);
        #pragma unroll
        for (int k = 0; k < 9; ++k) {
            float m0, m1;
            unpk2(m0, m1, m[k]);
            FMA9(yacc, dup2(m0), sV + (2*k)*20);
            FMA9(yacc, dup2(m1), sV + (2*k+1)*20);
        }
        ST9(sN + pixl*360 + j*20, yacc);
        __syncthreads();
        float* ob = outp + segbase;
        for (int e = t; e < 1296; e += 288) {
            int p_idx = e/81, c4 = (e - p_idx*81)*4;
            *(float4*)(ob + 4*e) = gather4(sN + p_idx*360, c4);
        }
        for (int e = t; e < 324; e += 288) {
            int a = e/18, d = e - a*18;
            float s = 0.f, ss = 0.f;
            #pragma unroll 4
            for (int pp = 0; pp < 16; ++pp) {
                float v = sN[pp*360 + a*20 + d];
                s += v; ss = fmaf(v, v, ss);
            }
            psum[e*PSTRIDE + blockIdx.x] = s;
            psq [e*PSTRIDE + blockIdx.x] = ss;
        }
        __syncthreads();
    }
}

// ---------------- conv3x3 v3: register-M, per-di weights, 4 blocks/SM ----------------
__global__ void __launch_bounds__(288,4) conv3x3_kernel(
    const float* __restrict__ in, int slot, const float* __restrict__ alpha_ptr,
    const float* __restrict__ U9, const float* __restrict__ V9,
    const float* __restrict__ bm, float* __restrict__ out)
{
    extern __shared__ float sm[];
    float* sV3  = sm;            // 1080 (3 taps) [tap3][q*20+d]
    float* sU3  = sm + 1080;     // 1080 (3 taps) [tap3][a*20+p]
    float* sBp  = sm + 2160;     // 360
    float* sSc  = sm + 2520;     // 324
    float* sSh  = sm + 2844;     // 324
    float* sXa  = sm + 3168;     // 6480 — reused as sN at the end
    // total 9648 floats = 38592 B -> 4 blocks/SM
    const int t = threadIdx.x;
    const int j = t % 18, pixl = t / 18;

    for (int e = t; e < 360; e += 288) { int q = e/20, d = e%20; sBp[e] = (d < 18) ? bm[q*18 + d] : 0.f; }
    for (int e = t; e < 324; e += 288) { sSc[e] = g_scale[slot][e]; sSh[e] = g_shift[slot][e]; }
    const float alpha = *alpha_ptr;

    const int pixbase = blockIdx.x * 16;
    const int hwb = pixbase & 1023;
    const int hh = hwb >> 5, wb = hwb & 31;
    u64 yacc[9];
    __syncthreads();
    LD9BIAS(yacc, sBp + j*20);

    for (int di = 0; di < 3; ++di) {
        const int hr = hh + di - 1;
        const bool rowok = (unsigned)hr < 32u;
        __syncthreads();   // previous di's readers of sXa / weights done
        // stage this di's 3 taps of weights
        for (int e = t; e < 1080; e += 288) {
            int tap3 = e/360, r = e%360, q = r/20, d = r%20;
            sV3[e] = (d < 18) ? V9[((di*3 + tap3)*18 + q)*18 + d] : 0.f;
            sU3[e] = (d < 18) ? U9[(di*3 + tap3)*324 + q*18 + d] : 0.f;  // row a=q, col p=d
        }
        // stage 18 activated pixel tensors of row hr (cols wb-1..wb+16), pitch-20 rows
        for (int e = t; e < 5832; e += 288) {
            int px = e / 324, rc = e - px*324;
            int gw = wb + px - 1;
            float r = 0.f;
            if (rowok && (unsigned)gw < 32u) {
                float v = in[(size_t)(pixbase + (di-1)*32 + px - 1)*324 + rc];
                r = fmaf(v, sSc[rc], sSh[rc]);
                if (r < 0.f) r *= alpha;
            }
            int p = rc / 18, q = rc - p*18;
            sXa[px*360 + p*20 + q] = r;
        }
        __syncthreads();
        if (rowok) {
            #pragma unroll
            for (int dj = 0; dj < 3; ++dj) {
                const int giw = wb + pixl + dj - 1;
                if ((unsigned)giw < 32u) {
                    const float* Xb = sXa + (pixl + dj)*360;
                    const float* Up = sU3 + dj*360 + j*20;
                    u64 m[9];
                    #pragma unroll
                    for (int k = 0; k < 9; ++k) m[k] = 0ull;
                    PHASE1_M9(m, Up, Xb);
                    #pragma unroll
                    for (int k = 0; k < 9; ++k) {
                        float m0, m1;
                        unpk2(m0, m1, m[k]);
                        FMA9(yacc, dup2(m0), sV3 + dj*360 + (2*k)*20);
                        FMA9(yacc, dup2(m1), sV3 + dj*360 + (2*k+1)*20);
                    }
                }
            }
        }
    }
    __syncthreads();   // done reading sXa; reuse as sN
    float* sN = sXa;
    ST9(sN + pixl*360 + j*20, yacc);
    __syncthreads();
    float* ob = out + (size_t)pixbase*324;
    for (int e = t; e < 1296; e += 288) {
        int p_idx = e/81, c4 = (e - p_idx*81)*4;
        *(float4*)(ob + 4*e) = gather4(sN + p_idx*360, c4);
    }
    for (int e = t; e < 324; e += 288) {
        int a = e/18, d = e - a*18;
        float s = 0.f, ss = 0.f;
        #pragma unroll 4
        for (int pp = 0; pp < 16; ++pp) {
            float v = sN[pp*360 + a*20 + d];
            s += v; ss = fmaf(v, v, ss);
        }
        g_psum0[e*PSTRIDE + blockIdx.x] = s;
        g_psq0 [e*PSTRIDE + blockIdx.x] = ss;
    }
}

// ---------------- finalize ----------------
__global__ void __launch_bounds__(256) finalize_kernel(
    const float* __restrict__ psum, const float* __restrict__ psq,
    const float* __restrict__ gamma, const float* __restrict__ beta,
    int slot, int nblk)
{
    const int pos = blockIdx.x, t = threadIdx.x;
    float s = 0.f, ss = 0.f;
    const float4* pa = (const float4*)(psum + (size_t)pos*PSTRIDE);
    const float4* pb = (const float4*)(psq  + (size_t)pos*PSTRIDE);
    for (int i = t; i < (nblk >> 2); i += 256) {
        float4 a = pa[i], b = pb[i];
        s  += (a.x + a.y) + (a.z + a.w);
        ss += (b.x + b.y) + (b.z + b.w);
    }
    #pragma unroll
    for (int o = 16; o > 0; o >>= 1) {
        s  += __shfl_down_sync(0xffffffffu, s,  o);
        ss += __shfl_down_sync(0xffffffffu, ss, o);
    }
    __shared__ float rs[8], rq[8];
    if ((t & 31) == 0) { rs[t>>5] = s; rq[t>>5] = ss; }
    __syncthreads();
    if (t == 0) {
        s = 0.f; ss = 0.f;
        #pragma unroll
        for (int i = 0; i < 8; ++i) { s += rs[i]; ss += rq[i]; }
        float mean = s * (1.f/32768.f);
        float var  = ss * (1.f/32768.f) - mean*mean;
        float inv  = rsqrtf(var + 1e-5f);
        float sc   = gamma[pos]*inv;
        g_scale[slot][pos] = sc;
        g_shift[slot][pos] = beta[pos] - mean*sc;
    }
}

// ---------------- head ----------------
__global__ void __launch_bounds__(324) head_kernel(
    const float* __restrict__ a, int slotA,
    const float* __restrict__ b, int slotB,
    const float* __restrict__ Wf, const float* __restrict__ bf,
    float* __restrict__ out) {
    __shared__ float sW[3240], sX[324], sPart[180];
    const int t = threadIdx.x;
    for (int e = t; e < 3240; e += 324) sW[e] = Wf[e];
    const float sA = g_scale[slotA][t], hA = g_shift[slotA][t];
    const float sB = g_scale[slotB][t], hB = g_shift[slotB][t];
    __syncthreads();
    const int pix0 = blockIdx.x * 8;
    for (int k = 0; k < 8; ++k) {
        const int pix = pix0 + k;
        const size_t base = (size_t)pix * 324;
        sX[t] = fmaf(a[base+t], sA, hA) + fmaf(b[base+t], sB, hB);
        __syncthreads();
        if (t < 180) {
            const int o = t/18, p = t - o*18;
            const float* xr = sX + p*18;
            const float* wr = sW + o*324 + p*18;
            float s = 0.f;
            #pragma unroll
            for (int q = 0; q < 18; ++q) s = fmaf(xr[q], wr[q], s);
            sPart[t] = s;
        }
        __syncthreads();
        if (t < 10) {
            float r = bf[t];
            #pragma unroll
            for (int p = 0; p < 18; ++p) r += sPart[t*18 + p];
            const int bb = pix >> 10, hw = pix & 1023;
            out[(size_t)(bb*10 + t)*1024 + hw] = r;
        }
        __syncthreads();
    }
}

// ---------------- host ----------------
extern "C" void kernel_launch(void* const* d_in, const int* in_sizes, int n_in,
                              void* d_out, int out_size) {
    (void)in_sizes; (void)n_in; (void)out_size;
    const float* x     = (const float*)d_in[0];
    const float* U0    = (const float*)d_in[1];
    const float* V0    = (const float*)d_in[2];
    const float* b0    = (const float*)d_in[3];
    const float* U1    = (const float*)d_in[4];
    const float* V1    = (const float*)d_in[5];
    const float* b1    = (const float*)d_in[6];
    const float* U3    = (const float*)d_in[7];
    const float* V3    = (const float*)d_in[8];
    const float* b3    = (const float*)d_in[9];
    const float* Wf    = (const float*)d_in[10];
    const float* bf    = (const float*)d_in[11];
    const float* gamma = (const float*)d_in[12];
    const float* beta  = (const float*)d_in[13];
    const float* alpha = (const float*)d_in[14];
    float* out = (float*)d_out;

    float *bufA, *bufB, *bufC, *bufD, *bufE;
    float *ps0, *pq0, *ps1, *pq1;
    cudaGetSymbolAddress((void**)&bufA, g_bufA);
    cudaGetSymbolAddress((void**)&bufB, g_bufB);
    cudaGetSymbolAddress((void**)&bufC, g_bufC);
    cudaGetSymbolAddress((void**)&bufD, g_bufD);
    cudaGetSymbolAddress((void**)&bufE, g_bufE);
    cudaGetSymbolAddress((void**)&ps0, g_psum0);
    cudaGetSymbolAddress((void**)&pq0, g_psq0);
    cudaGetSymbolAddress((void**)&ps1, g_psum1);
    cudaGetSymbolAddress((void**)&pq1, g_psq1);

    const int F0_SMEM = 12264 * 4;   //  49056 B
    const int C1_SMEM = 14976 * 4;   //  59904 B
    const int C3_SMEM =  9648 * 4;   //  38592 B
    cudaFuncSetAttribute(f0_kernel,      cudaFuncAttributeMaxDynamicSharedMemorySize, F0_SMEM);
    cudaFuncSetAttribute(conv1x1_kernel, cudaFuncAttributeMaxDynamicSharedMemorySize, C1_SMEM);
    cudaFuncSetAttribute(conv3x3_kernel, cudaFuncAttributeMaxDynamicSharedMemorySize, C3_SMEM);

    #define FIN0(slot, grow, nb) finalize_kernel<<<324,256>>>(ps0, pq0, gamma + (grow)*324, beta + (grow)*324, (slot), (nb))
    #define FIN1(slot, grow, nb) finalize_kernel<<<324,256>>>(ps1, pq1, gamma + (grow)*324, beta + (grow)*324, (slot), (nb))

    // profiler alignment: dual conv1x1 at launch #4
    dummy_kernel<<<1,32>>>();

    // f0 -> A (raw h), stats slot0 (gamma 0)
    f0_kernel<<<dim3(64,32), 288, F0_SMEM>>>(x, U0, V0, b0, bufA);
    FIN0(0, 0, 2048);

    // ---- block 1: dual-out (s1 -> B, t1 -> D) from prelu(bn(A,0)) ----
    conv1x1_kernel<<<2048,288,C1_SMEM>>>(bufA, 0, nullptr, 0, alpha+0,
        U1+0*324, V1+0*324, b1+0*324, bufB,
        U1+1*324, V1+1*324, b1+1*324, bufD);
    FIN0(1, 1, 2048); FIN1(2, 2, 2048);
    conv3x3_kernel<<<2048,288,C3_SMEM>>>(bufD, 2, alpha+1, U3+0*2916, V3+0*2916, b3+0*324, bufE);
    FIN0(3, 3, 2048);
    conv1x1_kernel<<<2048,288,C1_SMEM>>>(bufE, 3, nullptr, 0, alpha+2,
        U1+2*324, V1+2*324, b1+2*324, bufD,
        nullptr, nullptr, nullptr, nullptr);
    FIN0(4, 4, 2048);

    // ---- block 2: input x11 = bn(D,4)+bn(B,1); dual-out (s2 -> C, t1 -> A) ----
    conv1x1_kernel<<<2048,288,C1_SMEM>>>(bufD, 4, bufB, 1, nullptr,
        U1+3*324, V1+3*324, b1+3*324, bufC,
        U1+4*324, V1+4*324, b1+4*324, bufA);
    FIN0(5, 5, 2048); FIN1(6, 6, 2048);
    conv3x3_kernel<<<2048,288,C3_SMEM>>>(bufA, 6, alpha+3, U3+1*2916, V3+1*2916, b3+1*324, bufE);
    FIN0(7, 7, 2048);
    conv1x1_kernel<<<2048,288,C1_SMEM>>>(bufE, 7, nullptr, 0, alpha+4,
        U1+5*324, V1+5*324, b1+5*324, bufD,
        nullptr, nullptr, nullptr, nullptr);
    FIN0(8, 8, 2048);

    // ---- block 3: input x21 = bn(D,8)+bn(C,5); single-out t1 -> A
    //      (bug-faithful: identity = bn(s2); U1[6]/gamma[9] conv unused) ----
    conv1x1_kernel<<<2048,288,C1_SMEM>>>(bufD, 8, bufC, 5, nullptr,
        U1+7*324, V1+7*324, b1+7*324, bufA,
        nullptr, nullptr, nullptr, nullptr);
    FIN0(9, 10, 2048);
    conv3x3_kernel<<<2048,288,C3_SMEM>>>(bufA, 9, alpha+5, U3+2*2916, V3+2*2916, b3+2*324, bufE);
    FIN0(10, 11, 2048);
    conv1x1_kernel<<<2048,288,C1_SMEM>>>(bufE, 10, nullptr, 0, alpha+6,
        U1+8*324, V1+8*324, b1+8*324, bufD,
        nullptr, nullptr, nullptr, nullptr);
    FIN0(11, 12, 2048);

    // head: out = <bn(t3,11) + bn(s2,5), Wf> + bf
    head_kernel<<<4096,324>>>(bufD, 11, bufC, 5, Wf, bf, out);
}

// round 17
// speedup vs baseline: 1.0766x; 1.0766x over previous
#include <cuda_runtime.h>
#include <cstdint>

typedef unsigned long long u64;

#define NPIX 32768
#define PSTRIDE 2048

// ---------------- scratch ----------------
__device__ float g_bufA[NPIX*324];
__device__ float g_bufB[NPIX*324];
__device__ float g_bufC[NPIX*324];
__device__ float g_bufD[NPIX*324];
__device__ float g_bufE[NPIX*324];

// transposed partials: [pos][blk], stride 2048
__device__ float g_psum0[324*PSTRIDE];
__device__ float g_psq0 [324*PSTRIDE];
__device__ float g_psum1[324*PSTRIDE];
__device__ float g_psq1 [324*PSTRIDE];
__device__ float g_scale[12][324];
__device__ float g_shift[12][324];

// ---------------- f32x2 helpers ----------------
__device__ __forceinline__ u64 pk2(float lo, float hi){ u64 r; asm("mov.b64 %0,{%1,%2};":"=l"(r):"f"(lo),"f"(hi)); return r; }
__device__ __forceinline__ u64 dup2(float v){ return pk2(v, v); }
__device__ __forceinline__ void fma2(u64 &d, u64 a, u64 b){ asm("fma.rn.f32x2 %0,%1,%2,%0;":"+l"(d):"l"(a),"l"(b)); }
__device__ __forceinline__ void unpk2(float &lo, float &hi, u64 v){ asm("mov.b64 {%0,%1},%2;":"=f"(lo),"=f"(hi):"l"(v)); }

#define FMA9(acc, xd, vbase) { \
  const ulonglong2* _vv = (const ulonglong2*)(vbase); \
  ulonglong2 _a0=_vv[0], _a1=_vv[1], _a2=_vv[2], _a3=_vv[3]; \
  u64 _a8 = ((const u64*)(vbase))[8]; \
  fma2(acc[0],xd,_a0.x); fma2(acc[1],xd,_a0.y); \
  fma2(acc[2],xd,_a1.x); fma2(acc[3],xd,_a1.y); \
  fma2(acc[4],xd,_a2.x); fma2(acc[5],xd,_a2.y); \
  fma2(acc[6],xd,_a3.x); fma2(acc[7],xd,_a3.y); \
  fma2(acc[8],xd,_a8); }

// m[0..7] += ud * X[p][0..15] (16 contiguous floats, 4x LDS.128)
#define FMA8X(m, ud, xb) { \
  const ulonglong2* _xp = (const ulonglong2*)(xb); \
  ulonglong2 _x0=_xp[0], _x1=_xp[1], _x2=_xp[2], _x3=_xp[3]; \
  fma2(m[0],ud,_x0.x); fma2(m[1],ud,_x0.y); \
  fma2(m[2],ud,_x1.x); fma2(m[3],ud,_x1.y); \
  fma2(m[4],ud,_x2.x); fma2(m[5],ud,_x2.y); \
  fma2(m[6],ud,_x3.x); fma2(m[7],ud,_x3.y); }

#define ST9(dst, acc) { \
  ulonglong2* _dd=(ulonglong2*)(dst); \
  _dd[0]=make_ulonglong2(acc[0],acc[1]); _dd[1]=make_ulonglong2(acc[2],acc[3]); \
  _dd[2]=make_ulonglong2(acc[4],acc[5]); _dd[3]=make_ulonglong2(acc[6],acc[7]); \
  ((u64*)(dst))[8]=acc[8]; }

#define LD9BIAS(yacc, bptr) { \
  const ulonglong2* _bb = (const ulonglong2*)(bptr); \
  ulonglong2 _b0=_bb[0], _b1=_bb[1], _b2=_bb[2], _b3=_bb[3]; \
  yacc[0]=_b0.x; yacc[1]=_b0.y; yacc[2]=_b1.x; yacc[3]=_b1.y; \
  yacc[4]=_b2.x; yacc[5]=_b2.y; yacc[6]=_b3.x; yacc[7]=_b3.y; \
  yacc[8]=((const u64*)(bptr))[8]; }

// gather 4 consecutive logical elements (c4..c4+3) of a pixel from pitch-20 rows
__device__ __forceinline__ float4 gather4(const float* sNp, int c4) {
    float4 o;
    int r0 = (c4+0)/18; o.x = sNp[r0*20 + (c4+0) - r0*18];
    int r1 = (c4+1)/18; o.y = sNp[r1*20 + (c4+1) - r1*18];
    int r2 = (c4+2)/18; o.z = sNp[r2*20 + (c4+2) - r2*18];
    int r3 = (c4+3)/18; o.w = sNp[r3*20 + (c4+3) - r3*18];
    return o;
}
// scatter 4 consecutive logical elements into pitch-20 rows
__device__ __forceinline__ void scatter4(float* sNp, int c4, float4 v) {
    int r0 = (c4+0)/18; sNp[r0*20 + (c4+0) - r0*18] = v.x;
    int r1 = (c4+1)/18; sNp[r1*20 + (c4+1) - r1*18] = v.y;
    int r2 = (c4+2)/18; sNp[r2*20 + (c4+2) - r2*18] = v.z;
    int r3 = (c4+3)/18; sNp[r3*20 + (c4+3) - r3*18] = v.w;
}

// phase1 with vector-loaded U row (pitch 20, 18 valid) against pitch-20 X rows
#define PHASE1_M9(m, Up, Xb) { \
  float4 _u; float2 _ue; \
  _u = *(const float4*)((Up)+0); \
  FMA9(m, dup2(_u.x), (Xb)+0*20); FMA9(m, dup2(_u.y), (Xb)+1*20); \
  FMA9(m, dup2(_u.z), (Xb)+2*20); FMA9(m, dup2(_u.w), (Xb)+3*20); \
  _u = *(const float4*)((Up)+4); \
  FMA9(m, dup2(_u.x), (Xb)+4*20); FMA9(m, dup2(_u.y), (Xb)+5*20); \
  FMA9(m, dup2(_u.z), (Xb)+6*20); FMA9(m, dup2(_u.w), (Xb)+7*20); \
  _u = *(const float4*)((Up)+8); \
  FMA9(m, dup2(_u.x), (Xb)+8*20); FMA9(m, dup2(_u.y), (Xb)+9*20); \
  FMA9(m, dup2(_u.z), (Xb)+10*20); FMA9(m, dup2(_u.w), (Xb)+11*20); \
  _u = *(const float4*)((Up)+12); \
  FMA9(m, dup2(_u.x), (Xb)+12*20); FMA9(m, dup2(_u.y), (Xb)+13*20); \
  FMA9(m, dup2(_u.z), (Xb)+14*20); FMA9(m, dup2(_u.w), (Xb)+15*20); \
  _ue = *(const float2*)((Up)+16); \
  FMA9(m, dup2(_ue.x), (Xb)+16*20); FMA9(m, dup2(_ue.y), (Xb)+17*20); }

// ---------------- dummy (profiler alignment) ----------------
__global__ void dummy_kernel() {}

// ---------------- f0: (U·X)·V order, scalar U broadcast (R13/R14 proven) ----------------
__global__ void __launch_bounds__(288,4) f0_kernel(const float* __restrict__ x,
    const float* __restrict__ U0, const float* __restrict__ V0,
    const float* __restrict__ b0, float* __restrict__ out)
{
    extern __shared__ float sm[];
    float* sT  = sm;              // 18*260 = 4680
    float* sU  = sm + 4680;       // 864  (3 taps) [tap3][p*18+a]
    float* sVp = sm + 5544;       // 960  (3 taps) [tap3][q*20+d]
    float* sN  = sm + 6504;       // 5760 -> total 12264 floats
    const int t = threadIdx.x;
    const int j = t % 18, pixl = t / 18;
    const int hx = blockIdx.x, b = blockIdx.y;
    const int h = hx >> 1, wbase = (hx & 1) << 4;
    const int gbid = b*64 + hx;

    u64 yacc[9];
    #pragma unroll
    for (int k = 0; k < 9; ++k) yacc[k] = *(const u64*)(b0 + j*18 + 2*k);

    for (int c = 0; c < 8; ++c) {
        const float* xc  = x  + (size_t)(b*8 + c)*262144;
        const float* U0c = U0 + c*2592;
        const float* V0c = V0 + c*2592;
        for (int di = 0; di < 3; ++di) {
            const int hr = h - 1 + di;
            for (int e = t; e < 864; e += 288) {
                int tap3 = e/288, r = e%288, a = r/16, p = r%16;
                sU[tap3*288 + p*18 + a] = U0c[(di*3 + tap3)*288 + r];
            }
            for (int e = t; e < 960; e += 288) {
                int tap3 = e/320, r = e%320, q = r/20, d = r%20;
                sVp[e] = (d < 18) ? V0c[((di*3 + tap3)*16 + q)*18 + d] : 0.f;
            }
            for (int e = t; e < 4608; e += 288) {
                int pq = e/18, col = e - (e/18)*18;
                int gw = wbase - 1 + col;
                float v = 0.f;
                if ((unsigned)hr < 32u && (unsigned)gw < 32u)
                    v = xc[pq*1024 + hr*32 + gw];
                sT[col*260 + pq] = v;
            }
            __syncthreads();
            #pragma unroll
            for (int dj = 0; dj < 3; ++dj) {
                const float* Xb = sT + (pixl + dj)*260;
                u64 m[8];
                #pragma unroll
                for (int k = 0; k < 8; ++k) m[k] = 0ull;
                #pragma unroll
                for (int p = 0; p < 16; ++p) {
                    u64 ud = dup2(sU[dj*288 + p*18 + j]);
                    FMA8X(m, ud, Xb + p*16);
                }
                #pragma unroll
                for (int k = 0; k < 8; ++k) {
                    float m0, m1;
                    unpk2(m0, m1, m[k]);
                    FMA9(yacc, dup2(m0), sVp + dj*320 + (2*k)*20);
                    FMA9(yacc, dup2(m1), sVp + dj*320 + (2*k+1)*20);
                }
            }
            __syncthreads();
        }
    }
    ST9(sN + pixl*360 + j*20, yacc);
    __syncthreads();
    float* ob = out + ((size_t)(b*32 + h)*32 + wbase)*324;
    for (int e = t; e < 1296; e += 288) {
        int p_idx = e/81, c4 = (e - p_idx*81)*4;
        *(float4*)(ob + 4*e) = gather4(sN + p_idx*360, c4);
    }
    for (int e = t; e < 324; e += 288) {
        int a = e/18, d = e - a*18;
        float s = 0.f, ss = 0.f;
        #pragma unroll 4
        for (int pp = 0; pp < 16; ++pp) {
            float v = sN[pp*360 + a*20 + d];
            s += v; ss = fmaf(v, v, ss);
        }
        g_psum0[e*PSTRIDE + gbid] = s;
        g_psq0 [e*PSTRIDE + gbid] = ss;
    }
}

// ---------------- conv1x1 v3 (R16, measured neutral-positive) ----------------
__global__ void __launch_bounds__(288,3) conv1x1_kernel(
    const float* __restrict__ inA, int slotA,
    const float* __restrict__ inB, int slotB,
    const float* __restrict__ alpha_ptr,
    const float* __restrict__ U0w, const float* __restrict__ V0w,
    const float* __restrict__ b0w, float* __restrict__ out0,
    const float* __restrict__ U1w, const float* __restrict__ V1w,
    const float* __restrict__ b1w, float* __restrict__ out1)
{
    extern __shared__ float sm[];
    float* sV0  = sm;            // 360 [q*20+d]
    float* sV1  = sm + 360;      // 360
    float* sU0  = sm + 720;      // 360 [a*20+p]
    float* sU1  = sm + 1080;     // 360
    float* sB0  = sm + 1440;     // 360
    float* sB1  = sm + 1800;     // 360
    float* sScA = sm + 2160;     // 324
    float* sShA = sm + 2484;     // 324
    float* sScB = sm + 2808;     // 324
    float* sShB = sm + 3132;     // 324
    float* sXa  = sm + 3456;     // 5760
    float* sN   = sm + 9216;     // 5760 -> total 14976 floats = 59904 B
    const int t = threadIdx.x;
    const int j = t % 18, pixl = t / 18;
    const bool dual_in  = (inB  != nullptr);
    const bool dual_out = (out1 != nullptr);

    for (int e = t; e < 360; e += 288) {
        int q = e/20, d = e%20;
        sV0[e] = (d < 18) ? V0w[q*18 + d] : 0.f;
        sB0[e] = (d < 18) ? b0w[q*18 + d] : 0.f;
        sU0[e] = (d < 18) ? U0w[q*18 + d] : 0.f;
        if (dual_out) {
            sV1[e] = (d < 18) ? V1w[q*18 + d] : 0.f;
            sB1[e] = (d < 18) ? b1w[q*18 + d] : 0.f;
            sU1[e] = (d < 18) ? U1w[q*18 + d] : 0.f;
        }
    }
    for (int e = t; e < 324; e += 288) {
        sScA[e] = g_scale[slotA][e];
        sShA[e] = g_shift[slotA][e];
        if (dual_in) { sScB[e] = g_scale[slotB][e]; sShB[e] = g_shift[slotB][e]; }
    }
    const float alpha = (!dual_in && alpha_ptr) ? *alpha_ptr : 1.f;
    __syncthreads();

    const size_t segbase = (size_t)blockIdx.x * 5184;
    const float* gA = inA + segbase;
    const float* gB = dual_in ? (inB + segbase) : nullptr;
    for (int e = t; e < 1296; e += 288) {
        float4 v = *(const float4*)(gA + 4*e);
        int px = e / 81, c4 = (e - px*81) * 4;
        float4 sc = *(const float4*)(sScA + c4);
        float4 sh = *(const float4*)(sShA + c4);
        float4 r;
        r.x = fmaf(v.x, sc.x, sh.x);
        r.y = fmaf(v.y, sc.y, sh.y);
        r.z = fmaf(v.z, sc.z, sh.z);
        r.w = fmaf(v.w, sc.w, sh.w);
        if (dual_in) {
            float4 vb  = *(const float4*)(gB + 4*e);
            float4 scb = *(const float4*)(sScB + c4);
            float4 shb = *(const float4*)(sShB + c4);
            r.x += fmaf(vb.x, scb.x, shb.x);
            r.y += fmaf(vb.y, scb.y, shb.y);
            r.z += fmaf(vb.z, scb.z, shb.z);
            r.w += fmaf(vb.w, scb.w, shb.w);
        } else {
            if (r.x < 0.f) r.x *= alpha;
            if (r.y < 0.f) r.y *= alpha;
            if (r.z < 0.f) r.z *= alpha;
            if (r.w < 0.f) r.w *= alpha;
        }
        scatter4(sXa + px*360, c4, r);
    }
    __syncthreads();

    for (int pass = 0; pass < (dual_out ? 2 : 1); ++pass) {
        const float* sV  = pass ? sV1 : sV0;
        const float* sU  = pass ? sU1 : sU0;
        const float* sBp = pass ? sB1 : sB0;
        float* outp      = pass ? out1 : out0;
        float* psum      = pass ? g_psum1 : g_psum0;
        float* psq       = pass ? g_psq1  : g_psq0;

        u64 m[9];
        #pragma unroll
        for (int k = 0; k < 9; ++k) m[k] = 0ull;
        const float* Xb = sXa + pixl*360;
        const float* Up = sU + j*20;
        PHASE1_M9(m, Up, Xb);

        u64 yacc[9];
        LD9BIAS(yacc, sBp + j*20);
        #pragma unroll
        for (int k = 0; k < 9; ++k) {
            float m0, m1;
            unpk2(m0, m1, m[k]);
            FMA9(yacc, dup2(m0), sV + (2*k)*20);
            FMA9(yacc, dup2(m1), sV + (2*k+1)*20);
        }
        ST9(sN + pixl*360 + j*20, yacc);
        __syncthreads();
        float* ob = outp + segbase;
        for (int e = t; e < 1296; e += 288) {
            int p_idx = e/81, c4 = (e - p_idx*81)*4;
            *(float4*)(ob + 4*e) = gather4(sN + p_idx*360, c4);
        }
        for (int e = t; e < 324; e += 288) {
            int a = e/18, d = e - a*18;
            float s = 0.f, ss = 0.f;
            #pragma unroll 4
            for (int pp = 0; pp < 16; ++pp) {
                float v = sN[pp*360 + a*20 + d];
                s += v; ss = fmaf(v, v, ss);
            }
            psum[e*PSTRIDE + blockIdx.x] = s;
            psq [e*PSTRIDE + blockIdx.x] = ss;
        }
        __syncthreads();
    }
}

// ---------------- conv3x3 v4: R14 register-M + scalar-U, per-di weights, 4 blocks/SM ----------------
__global__ void __launch_bounds__(288,4) conv3x3_kernel(
    const float* __restrict__ in, int slot, const float* __restrict__ alpha_ptr,
    const float* __restrict__ U9, const float* __restrict__ V9,
    const float* __restrict__ bm, float* __restrict__ out)
{
    extern __shared__ float sm[];
    float* sV3  = sm;            // 1080 (3 taps) [tap3][q*20+d]
    float* sU3  = sm + 1080;     // 972  (3 taps) [tap3][p*18+a]
    float* sBp  = sm + 2052;     // 360
    float* sSc  = sm + 2412;     // 324
    float* sSh  = sm + 2736;     // 324
    float* sXa  = sm + 3060;     // 6480 — reused as sN at the end
    // total 9540 floats = 38160 B -> 4 blocks/SM
    const int t = threadIdx.x;
    const int j = t % 18, pixl = t / 18;

    for (int e = t; e < 360; e += 288) { int q = e/20, d = e%20; sBp[e] = (d < 18) ? bm[q*18 + d] : 0.f; }
    for (int e = t; e < 324; e += 288) { sSc[e] = g_scale[slot][e]; sSh[e] = g_shift[slot][e]; }
    const float alpha = *alpha_ptr;

    const int pixbase = blockIdx.x * 16;
    const int hwb = pixbase & 1023;
    const int hh = hwb >> 5, wb = hwb & 31;
    u64 yacc[9];
    __syncthreads();
    LD9BIAS(yacc, sBp + j*20);

    for (int di = 0; di < 3; ++di) {
        const int hr = hh + di - 1;
        const bool rowok = (unsigned)hr < 32u;
        __syncthreads();   // previous di's readers of sXa / weights done
        // stage this di's 3 taps of weights
        for (int e = t; e < 1080; e += 288) {
            int tap3 = e/360, r = e%360, q = r/20, d = r%20;
            sV3[e] = (d < 18) ? V9[((di*3 + tap3)*18 + q)*18 + d] : 0.f;
        }
        for (int e = t; e < 972; e += 288) {
            int tap3 = e/324, r = e%324, a = r/18, p = r%18;
            sU3[tap3*324 + p*18 + a] = U9[(di*3 + tap3)*324 + r];
        }
        // stage 18 activated pixel tensors of row hr (cols wb-1..wb+16), pitch-20 rows
        for (int e = t; e < 5832; e += 288) {
            int px = e / 324, rc = e - px*324;
            int gw = wb + px - 1;
            float r = 0.f;
            if (rowok && (unsigned)gw < 32u) {
                float v = in[(size_t)(pixbase + (di-1)*32 + px - 1)*324 + rc];
                r = fmaf(v, sSc[rc], sSh[rc]);
                if (r < 0.f) r *= alpha;
            }
            int p = rc / 18, q = rc - p*18;
            sXa[px*360 + p*20 + q] = r;
        }
        __syncthreads();
        if (rowok) {
            #pragma unroll
            for (int dj = 0; dj < 3; ++dj) {
                const int giw = wb + pixl + dj - 1;
                if ((unsigned)giw < 32u) {
                    const float* Xb = sXa + (pixl + dj)*360;
                    u64 m[9];
                    #pragma unroll
                    for (int k = 0; k < 9; ++k) m[k] = 0ull;
                    #pragma unroll
                    for (int p = 0; p < 18; ++p) {
                        u64 ud = dup2(sU3[dj*324 + p*18 + j]);
                        FMA9(m, ud, Xb + p*20);
                    }
                    #pragma unroll
                    for (int k = 0; k < 9; ++k) {
                        float m0, m1;
                        unpk2(m0, m1, m[k]);
                        FMA9(yacc, dup2(m0), sV3 + dj*360 + (2*k)*20);
                        FMA9(yacc, dup2(m1), sV3 + dj*360 + (2*k+1)*20);
                    }
                }
            }
        }
    }
    __syncthreads();   // done reading sXa; reuse as sN
    float* sN = sXa;
    ST9(sN + pixl*360 + j*20, yacc);
    __syncthreads();
    float* ob = out + (size_t)pixbase*324;
    for (int e = t; e < 1296; e += 288) {
        int p_idx = e/81, c4 = (e - p_idx*81)*4;
        *(float4*)(ob + 4*e) = gather4(sN + p_idx*360, c4);
    }
    for (int e = t; e < 324; e += 288) {
        int a = e/18, d = e - a*18;
        float s = 0.f, ss = 0.f;
        #pragma unroll 4
        for (int pp = 0; pp < 16; ++pp) {
            float v = sN[pp*360 + a*20 + d];
            s += v; ss = fmaf(v, v, ss);
        }
        g_psum0[e*PSTRIDE + blockIdx.x] = s;
        g_psq0 [e*PSTRIDE + blockIdx.x] = ss;
    }
}

// ---------------- finalize ----------------
__global__ void __launch_bounds__(256) finalize_kernel(
    const float* __restrict__ psum, const float* __restrict__ psq,
    const float* __restrict__ gamma, const float* __restrict__ beta,
    int slot, int nblk)
{
    const int pos = blockIdx.x, t = threadIdx.x;
    float s = 0.f, ss = 0.f;
    const float4* pa = (const float4*)(psum + (size_t)pos*PSTRIDE);
    const float4* pb = (const float4*)(psq  + (size_t)pos*PSTRIDE);
    for (int i = t; i < (nblk >> 2); i += 256) {
        float4 a = pa[i], b = pb[i];
        s  += (a.x + a.y) + (a.z + a.w);
        ss += (b.x + b.y) + (b.z + b.w);
    }
    #pragma unroll
    for (int o = 16; o > 0; o >>= 1) {
        s  += __shfl_down_sync(0xffffffffu, s,  o);
        ss += __shfl_down_sync(0xffffffffu, ss, o);
    }
    __shared__ float rs[8], rq[8];
    if ((t & 31) == 0) { rs[t>>5] = s; rq[t>>5] = ss; }
    __syncthreads();
    if (t == 0) {
        s = 0.f; ss = 0.f;
        #pragma unroll
        for (int i = 0; i < 8; ++i) { s += rs[i]; ss += rq[i]; }
        float mean = s * (1.f/32768.f);
        float var  = ss * (1.f/32768.f) - mean*mean;
        float inv  = rsqrtf(var + 1e-5f);
        float sc   = gamma[pos]*inv;
        g_scale[slot][pos] = sc;
        g_shift[slot][pos] = beta[pos] - mean*sc;
    }
}

// ---------------- head ----------------
__global__ void __launch_bounds__(324) head_kernel(
    const float* __restrict__ a, int slotA,
    const float* __restrict__ b, int slotB,
    const float* __restrict__ Wf, const float* __restrict__ bf,
    float* __restrict__ out) {
    __shared__ float sW[3240], sX[324], sPart[180];
    const int t = threadIdx.x;
    for (int e = t; e < 3240; e += 324) sW[e] = Wf[e];
    const float sA = g_scale[slotA][t], hA = g_shift[slotA][t];
    const float sB = g_scale[slotB][t], hB = g_shift[slotB][t];
    __syncthreads();
    const int pix0 = blockIdx.x * 8;
    for (int k = 0; k < 8; ++k) {
        const int pix = pix0 + k;
        const size_t base = (size_t)pix * 324;
        sX[t] = fmaf(a[base+t], sA, hA) + fmaf(b[base+t], sB, hB);
        __syncthreads();
        if (t < 180) {
            const int o = t/18, p = t - o*18;
            const float* xr = sX + p*18;
            const float* wr = sW + o*324 + p*18;
            float s = 0.f;
            #pragma unroll
            for (int q = 0; q < 18; ++q) s = fmaf(xr[q], wr[q], s);
            sPart[t] = s;
        }
        __syncthreads();
        if (t < 10) {
            float r = bf[t];
            #pragma unroll
            for (int p = 0; p < 18; ++p) r += sPart[t*18 + p];
            const int bb = pix >> 10, hw = pix & 1023;
            out[(size_t)(bb*10 + t)*1024 + hw] = r;
        }
        __syncthreads();
    }
}

// ---------------- host ----------------
extern "C" void kernel_launch(void* const* d_in, const int* in_sizes, int n_in,
                              void* d_out, int out_size) {
    (void)in_sizes; (void)n_in; (void)out_size;
    const float* x     = (const float*)d_in[0];
    const float* U0    = (const float*)d_in[1];
    const float* V0    = (const float*)d_in[2];
    const float* b0    = (const float*)d_in[3];
    const float* U1    = (const float*)d_in[4];
    const float* V1    = (const float*)d_in[5];
    const float* b1    = (const float*)d_in[6];
    const float* U3    = (const float*)d_in[7];
    const float* V3    = (const float*)d_in[8];
    const float* b3    = (const float*)d_in[9];
    const float* Wf    = (const float*)d_in[10];
    const float* bf    = (const float*)d_in[11];
    const float* gamma = (const float*)d_in[12];
    const float* beta  = (const float*)d_in[13];
    const float* alpha = (const float*)d_in[14];
    float* out = (float*)d_out;

    float *bufA, *bufB, *bufC, *bufD, *bufE;
    float *ps0, *pq0, *ps1, *pq1;
    cudaGetSymbolAddress((void**)&bufA, g_bufA);
    cudaGetSymbolAddress((void**)&bufB, g_bufB);
    cudaGetSymbolAddress((void**)&bufC, g_bufC);
    cudaGetSymbolAddress((void**)&bufD, g_bufD);
    cudaGetSymbolAddress((void**)&bufE, g_bufE);
    cudaGetSymbolAddress((void**)&ps0, g_psum0);
    cudaGetSymbolAddress((void**)&pq0, g_psq0);
    cudaGetSymbolAddress((void**)&ps1, g_psum1);
    cudaGetSymbolAddress((void**)&pq1, g_psq1);

    const int F0_SMEM = 12264 * 4;   //  49056 B
    const int C1_SMEM = 14976 * 4;   //  59904 B
    const int C3_SMEM =  9540 * 4;   //  38160 B
    cudaFuncSetAttribute(f0_kernel,      cudaFuncAttributeMaxDynamicSharedMemorySize, F0_SMEM);
    cudaFuncSetAttribute(conv1x1_kernel, cudaFuncAttributeMaxDynamicSharedMemorySize, C1_SMEM);
    cudaFuncSetAttribute(conv3x3_kernel, cudaFuncAttributeMaxDynamicSharedMemorySize, C3_SMEM);

    #define FIN0(slot, grow, nb) finalize_kernel<<<324,256>>>(ps0, pq0, gamma + (grow)*324, beta + (grow)*324, (slot), (nb))
    #define FIN1(slot, grow, nb) finalize_kernel<<<324,256>>>(ps1, pq1, gamma + (grow)*324, beta + (grow)*324, (slot), (nb))

    // profiler alignment: dual conv1x1 at launch #4
    dummy_kernel<<<1,32>>>();

    // f0 -> A (raw h), stats slot0 (gamma 0)
    f0_kernel<<<dim3(64,32), 288, F0_SMEM>>>(x, U0, V0, b0, bufA);
    FIN0(0, 0, 2048);

    // ---- block 1: dual-out (s1 -> B, t1 -> D) from prelu(bn(A,0)) ----
    conv1x1_kernel<<<2048,288,C1_SMEM>>>(bufA, 0, nullptr, 0, alpha+0,
        U1+0*324, V1+0*324, b1+0*324, bufB,
        U1+1*324, V1+1*324, b1+1*324, bufD);
    FIN0(1, 1, 2048); FIN1(2, 2, 2048);
    conv3x3_kernel<<<2048,288,C3_SMEM>>>(bufD, 2, alpha+1, U3+0*2916, V3+0*2916, b3+0*324, bufE);
    FIN0(3, 3, 2048);
    conv1x1_kernel<<<2048,288,C1_SMEM>>>(bufE, 3, nullptr, 0, alpha+2,
        U1+2*324, V1+2*324, b1+2*324, bufD,
        nullptr, nullptr, nullptr, nullptr);
    FIN0(4, 4, 2048);

    // ---- block 2: input x11 = bn(D,4)+bn(B,1); dual-out (s2 -> C, t1 -> A) ----
    conv1x1_kernel<<<2048,288,C1_SMEM>>>(bufD, 4, bufB, 1, nullptr,
        U1+3*324, V1+3*324, b1+3*324, bufC,
        U1+4*324, V1+4*324, b1+4*324, bufA);
    FIN0(5, 5, 2048); FIN1(6, 6, 2048);
    conv3x3_kernel<<<2048,288,C3_SMEM>>>(bufA, 6, alpha+3, U3+1*2916, V3+1*2916, b3+1*324, bufE);
    FIN0(7, 7, 2048);
    conv1x1_kernel<<<2048,288,C1_SMEM>>>(bufE, 7, nullptr, 0, alpha+4,
        U1+5*324, V1+5*324, b1+5*324, bufD,
        nullptr, nullptr, nullptr, nullptr);
    FIN0(8, 8, 2048);

    // ---- block 3: input x21 = bn(D,8)+bn(C,5); single-out t1 -> A
    //      (bug-faithful: identity = bn(s2); U1[6]/gamma[9] conv unused) ----
    conv1x1_kernel<<<2048,288,C1_SMEM>>>(bufD, 8, bufC, 5, nullptr,
        U1+7*324, V1+7*324, b1+7*324, bufA,
        nullptr, nullptr, nullptr, nullptr);
    FIN0(9, 10, 2048);
    conv3x3_kernel<<<2048,288,C3_SMEM>>>(bufA, 9, alpha+5, U3+2*2916, V3+2*2916, b3+2*324, bufE);
    FIN0(10, 11, 2048);
    conv1x1_kernel<<<2048,288,C1_SMEM>>>(bufE, 10, nullptr, 0, alpha+6,
        U1+8*324, V1+8*324, b1+8*324, bufD,
        nullptr, nullptr, nullptr, nullptr);
    FIN0(11, 12, 2048);

    // head: out = <bn(t3,11) + bn(s2,5), Wf> + bf
    head_kernel<<<4096,324>>>(bufD, 11, bufC, 5, Wf, bf, out);
}